// round 3
// baseline (speedup 1.0000x reference)
#include <cuda_runtime.h>
#include <math.h>

#define BB 2
#define LL 2048
#define DM 1024
#define DIN 2048
#define NH 32
#define HD 64
#define DS 128
#define NA 32
#define NC 32
#define CK 64
#define DPROJ 4480
#define EPSF 1e-5f

// ---- scratch (device globals; no allocation allowed) ----
__device__ float g_proj[(size_t)BB*LL*DPROJ];     // 73 MB
__device__ float g_Q[(size_t)BB*LL*NH*DS];        // 67 MB
__device__ float g_K[(size_t)BB*LL*NH*DS];        // 67 MB
__device__ float g_dt[BB*LL*NH];
__device__ float g_adt[BB*LL*NH];
__device__ float g_g1[BB*LL*NH];
__device__ float g_g2[BB*LL*NH];
__device__ float g_theta[(size_t)BB*LL*NH*NA];    // 17 MB
__device__ float g_eell[BB*LL*NH];
__device__ float g_cd[BB*NC*NH];
__device__ float g_W[(size_t)BB*NC*NH*HD*DS];     // 67 MB (Wsum -> Hprevs in place)
__device__ float g_y[(size_t)BB*LL*DIN];          // 33 MB

__device__ __forceinline__ float sp_(float x){ return x > 20.f ? x : log1pf(expf(x)); }
__device__ __forceinline__ float sigm_(float x){ return 1.f/(1.f+expf(-x)); }

// ---------------- SGEMM: C[M,N] = A[M,K] @ B[K,N], all row-major ----------------
// BM=BN=128, BK=8, 256 threads, 8x8 per thread. All dims divide exactly here.
__global__ void __launch_bounds__(256) sgemm128(const float* __restrict__ A,
                                                const float* __restrict__ Bm,
                                                float* __restrict__ C,
                                                int M, int N, int K) {
  __shared__ float As[8][128];
  __shared__ float Bs[8][128];
  int t = threadIdx.x;
  int bx = blockIdx.x, by = blockIdx.y;
  int tx = t & 15, ty = t >> 4;
  int ar = t >> 1, ac = (t & 1) * 4;
  int br = t >> 5, bc = (t & 31) * 4;
  const float* Ap = A + (size_t)(by*128 + ar)*K + ac;
  const float* Bp = Bm + (size_t)br*N + bx*128 + bc;
  float acc[8][8];
  #pragma unroll
  for (int i=0;i<8;i++)
    #pragma unroll
    for (int j=0;j<8;j++) acc[i][j]=0.f;
  for (int k0=0;k0<K;k0+=8) {
    float4 a4 = *(const float4*)(Ap + k0);
    float4 b4 = *(const float4*)(Bp + (size_t)k0*N);
    As[ac+0][ar]=a4.x; As[ac+1][ar]=a4.y; As[ac+2][ar]=a4.z; As[ac+3][ar]=a4.w;
    *(float4*)&Bs[br][bc] = b4;
    __syncthreads();
    #pragma unroll
    for (int kk=0;kk<8;kk++){
      float a[8], b[8];
      *(float4*)(a)   = *(const float4*)&As[kk][ty*8];
      *(float4*)(a+4) = *(const float4*)&As[kk][ty*8+4];
      *(float4*)(b)   = *(const float4*)&Bs[kk][tx*8];
      *(float4*)(b+4) = *(const float4*)&Bs[kk][tx*8+4];
      #pragma unroll
      for (int i=0;i<8;i++)
        #pragma unroll
        for (int j=0;j<8;j++) acc[i][j] += a[i]*b[j];
    }
    __syncthreads();
  }
  #pragma unroll
  for (int i=0;i<8;i++){
    float* Cp = C + (size_t)(by*128 + ty*8 + i)*N + bx*128 + tx*8;
    *(float4*)Cp     = make_float4(acc[i][0],acc[i][1],acc[i][2],acc[i][3]);
    *(float4*)(Cp+4) = make_float4(acc[i][4],acc[i][5],acc[i][6],acc[i][7]);
  }
}

// ---------------- pointwise: dt, adt, g1, g2 ----------------
__global__ void k_point(const float* __restrict__ dt_bias) {
  int idx = blockIdx.x*256 + threadIdx.x;
  if (idx >= BB*LL*NH) return;
  int h = idx % NH; int bl = idx / NH; int l = bl % LL;
  size_t base = (size_t)bl * DPROJ;
  float db = dt_bias[h];
  float dt = sp_(g_proj[base + 4352 + h] + db);
  float a  = fminf(-sp_(g_proj[base + 4384 + h]), -1e-4f);
  float adt = a * dt;
  float beta = sigm_(g_proj[base + 4416 + h]);
  float dtp = (l > 0) ? sp_(g_proj[base - DPROJ + 4352 + h] + db) : 0.f;
  g_dt[idx]  = dt;
  g_adt[idx] = adt;
  g_g1[idx]  = beta * dt;
  g_g2[idx]  = (1.f - beta) * expf(adt) * dtp;
}

// ---------------- theta cumsum over L ----------------
__global__ void k_theta() {
  int b = blockIdx.x / NH, h = blockIdx.x % NH;
  int a = threadIdx.x;
  const float* pang = g_proj + (size_t)b*LL*DPROJ + 4448 + a;
  const float* pdt  = g_dt + (size_t)(b*LL)*NH + h;
  float* pth = g_theta + ((size_t)(b*LL)*NH + h)*NA + a;
  float th = 0.f;
  #pragma unroll 8
  for (int l=0;l<LL;l++){
    th += pang[(size_t)l*DPROJ] * pdt[(size_t)l*NH];
    pth[(size_t)l*NH*NA] = th;
  }
}

// ---------------- RMSNorm + bias + RoPE -> Q, K ----------------
__global__ void __launch_bounds__(128) k_qk(const float* __restrict__ B_bias,
                                            const float* __restrict__ C_bias,
                                            const float* __restrict__ Bw,
                                            const float* __restrict__ Cw) {
  int bl = blockIdx.x;
  int p = threadIdx.x;
  __shared__ float Bn[DS], Cn[DS];
  __shared__ float rs[4][2];
  size_t base = (size_t)bl * DPROJ;
  float bg = g_proj[base + 4096 + p];
  float cg = g_proj[base + 4224 + p];
  float sb = bg*bg, sc = cg*cg;
  #pragma unroll
  for (int o=16;o>0;o>>=1){
    sb += __shfl_xor_sync(0xffffffff, sb, o);
    sc += __shfl_xor_sync(0xffffffff, sc, o);
  }
  if ((p&31)==0){ rs[p>>5][0]=sb; rs[p>>5][1]=sc; }
  __syncthreads();
  float tb = rs[0][0]+rs[1][0]+rs[2][0]+rs[3][0];
  float tc = rs[0][1]+rs[1][1]+rs[2][1]+rs[3][1];
  float rB = rsqrtf(tb/(float)DS + EPSF);
  float rC = rsqrtf(tc/(float)DS + EPSF);
  Bn[p] = bg*rB*Bw[p];
  Cn[p] = cg*rC*Cw[p];
  __syncthreads();
  const float* th = g_theta + (size_t)bl*NH*NA;
  for (int h=0; h<NH; h++){
    float outK, outQ;
    if (p < 64) {
      int a = p & 31;
      float ang = th[h*NA + a];
      float c = cosf(ang), s = sinf(ang);
      if (p < 32) {
        float k1 = Bn[p]    + B_bias[h*DS+p];
        float k2 = Bn[p+32] + B_bias[h*DS+p+32];
        outK = k1*c - k2*s;
        float q1 = Cn[p]    + C_bias[h*DS+p];
        float q2 = Cn[p+32] + C_bias[h*DS+p+32];
        outQ = q1*c - q2*s;
      } else {
        float k1 = Bn[a] + B_bias[h*DS+a];
        float k2 = Bn[p] + B_bias[h*DS+p];
        outK = k1*s + k2*c;
        float q1 = Cn[a] + C_bias[h*DS+a];
        float q2 = Cn[p] + C_bias[h*DS+p];
        outQ = q1*s + q2*c;
      }
    } else {
      outK = Bn[p] + B_bias[h*DS+p];
      outQ = Cn[p] + C_bias[h*DS+p];
    }
    size_t o = ((size_t)bl*NH + h)*DS + p;
    g_K[o] = outK;
    g_Q[o] = outQ;
  }
}

// ---------------- chunk kernel: S1/S2, y_intra, Wsum ----------------
// one block per (b, c, h); dynamic smem
#define QSS 129
#define SMEM_CHUNK ((64*QSS + 65*QSS + 65*64 + 64*64*2)*4)
__global__ void __launch_bounds__(256) k_chunk() {
  extern __shared__ float sm[];
  float* Qs = sm;                  // 64 x 129
  float* Ke = Qs + 64*QSS;         // 65 x 129 (row r = token l0+r-1; Kc[j]=Ke[j+1], Kp[j]=Ke[j])
  float* xe = Ke + 65*QSS;         // 65 x 64
  float* S1 = xe + 65*64;          // 64 x 64
  float* S2 = S1 + 64*64;          // 64 x 64
  __shared__ float ell[CK], g1s[CK], g2s[CK], w1s[CK], w2s[CK];
  int t = threadIdx.x;
  int bid = blockIdx.x;
  int h = bid % NH; int c = (bid/NH) % NC; int b = bid/(NH*NC);
  int l0 = c*CK;
  size_t qbase = ((size_t)(b*LL + l0)*NH + h)*DS;
  for (int idx=t; idx<64*DS; idx+=256){
    int i = idx >> 7, n = idx & 127;
    Qs[i*QSS+n] = g_Q[qbase + (size_t)i*NH*DS + n];
  }
  for (int idx=t; idx<65*DS; idx+=256){
    int r = idx >> 7, n = idx & 127;
    int l = l0 + r - 1;
    Ke[r*QSS+n] = (l >= 0) ? g_K[((size_t)(b*LL + l)*NH + h)*DS + n] : 0.f;
  }
  for (int idx=t; idx<65*HD; idx+=256){
    int r = idx >> 6, pp = idx & 63;
    int l = l0 + r - 1;
    xe[r*64+pp] = (l >= 0) ? g_proj[(size_t)(b*LL + l)*DPROJ + DIN + h*HD + pp] : 0.f;
  }
  if (t < CK) {
    int gi = (b*LL + l0 + t)*NH + h;
    g1s[t] = g_g1[gi]; g2s[t] = g_g2[gi];
    ell[t] = g_adt[gi];
  }
  __syncthreads();
  if (t == 0) {
    float run = 0.f;
    for (int j=0;j<CK;j++){ run += ell[j]; ell[j] = run; }
  }
  __syncthreads();
  if (t < CK) {
    float e63 = ell[CK-1];
    float de = expf(e63 - ell[t]);
    w1s[t] = g1s[t]*de; w2s[t] = g2s[t]*de;
    g_eell[(b*LL + l0 + t)*NH + h] = expf(ell[t]);
    if (t == 0) g_cd[bid] = expf(e63);
  }
  __syncthreads();
  // Phase A: S1[i][j], S2[i][j]
  {
    int i = t >> 2;
    int js = (t & 3) * 16;
    float a1[16], a2[16];
    #pragma unroll
    for (int jj=0;jj<16;jj++){ a1[jj]=0.f; a2[jj]=0.f; }
    for (int n=0;n<DS;n++){
      float q = Qs[i*QSS+n];
      float kv[17];
      #pragma unroll
      for (int r=0;r<17;r++) kv[r] = Ke[(js+r)*QSS+n];
      #pragma unroll
      for (int jj=0;jj<16;jj++){
        a1[jj] += q*kv[jj+1];
        a2[jj] += q*kv[jj];
      }
    }
    float ei = ell[i];
    #pragma unroll
    for (int jj=0;jj<16;jj++){
      int j = js + jj;
      float d = (j <= i) ? expf(ei - ell[j]) : 0.f;
      S1[i*64+j] = a1[jj]*g1s[j]*d;
      S2[i*64+j] = a2[jj]*g2s[j]*d;
    }
  }
  __syncthreads();
  // Phase B: y_intra -> g_y
  {
    int i = t >> 2;
    int ps = (t & 3) * 16;
    float acc[16];
    #pragma unroll
    for (int pp=0;pp<16;pp++) acc[pp]=0.f;
    for (int j=0;j<=i;j++){
      float s1 = S1[i*64+j], s2 = S2[i*64+j];
      #pragma unroll
      for (int pp=0;pp<16;pp++)
        acc[pp] += s1*xe[(j+1)*64+ps+pp] + s2*xe[j*64+ps+pp];
    }
    size_t yb = (size_t)(b*LL + l0 + i)*DIN + h*HD + ps;
    #pragma unroll
    for (int pp=0;pp<16;pp++) g_y[yb+pp] = acc[pp];
  }
  // Phase C: Wsum[p][n] -> g_W  (no smem writes in B/C, no sync needed)
  {
    int p = t >> 2;
    int ns = (t & 3) * 32;
    float acc[32];
    #pragma unroll
    for (int nn=0;nn<32;nn++) acc[nn]=0.f;
    for (int j=0;j<CK;j++){
      float a1 = w1s[j]*xe[(j+1)*64+p];
      float a2 = w2s[j]*xe[j*64+p];
      #pragma unroll
      for (int nn=0;nn<32;nn++)
        acc[nn] += a1*Ke[(j+1)*QSS+ns+nn] + a2*Ke[j*QSS+ns+nn];
    }
    size_t wb = ((size_t)bid*HD + p)*DS + ns;
    #pragma unroll
    for (int nn=0;nn<32;nn++) g_W[wb+nn] = acc[nn];
  }
}

// ---------------- inter-chunk state scan (in place: Wsum -> Hprev) ----------------
__global__ void __launch_bounds__(256) k_scan() {
  int bh = blockIdx.x;
  int b = bh / NH, h = bh % NH;
  int t = threadIdx.x;
  float H[32];
  #pragma unroll
  for (int r=0;r<32;r++) H[r]=0.f;
  for (int c=0;c<NC;c++){
    int bid = (b*NC + c)*NH + h;
    size_t base = (size_t)bid * (HD*DS);
    float cd = g_cd[bid];
    #pragma unroll
    for (int r=0;r<32;r++){
      size_t e = base + t + r*256;
      float w = g_W[e];
      g_W[e] = H[r];
      H[r] = cd*H[r] + w;
    }
  }
}

// ---------------- y_inter + D*x + SiLU gating ----------------
#define SMEM_INTER ((64*QSS*2)*4)
__global__ void __launch_bounds__(256) k_inter(const float* __restrict__ Dp) {
  extern __shared__ float sm[];
  float* Hs = sm;             // 64(p) x 129(n)
  float* Qs = Hs + 64*QSS;    // 64(i) x 129(n)
  __shared__ float eel[CK];
  int t = threadIdx.x;
  int bid = blockIdx.x;
  int h = bid % NH; int c = (bid/NH)%NC; int b = bid/(NH*NC);
  int l0 = c*CK;
  size_t wbase = (size_t)bid*HD*DS;
  for (int idx=t; idx<HD*DS; idx+=256){
    int p = idx>>7, n = idx&127;
    Hs[p*QSS+n] = g_W[wbase + idx];
  }
  size_t qbase = ((size_t)(b*LL+l0)*NH + h)*DS;
  for (int idx=t; idx<CK*DS; idx+=256){
    int i = idx>>7, n = idx&127;
    Qs[i*QSS+n] = g_Q[qbase + (size_t)i*NH*DS + n];
  }
  if (t < CK) eel[t] = g_eell[(b*LL+l0+t)*NH + h];
  __syncthreads();
  int i = t>>2, ps = (t&3)*16;
  float acc[16];
  #pragma unroll
  for (int pp=0;pp<16;pp++) acc[pp]=0.f;
  for (int n=0;n<DS;n++){
    float q = Qs[i*QSS+n];
    #pragma unroll
    for (int pp=0;pp<16;pp++) acc[pp] += q*Hs[(ps+pp)*QSS+n];
  }
  float e = eel[i];
  float dv = Dp[h];
  size_t pb = (size_t)(b*LL+l0+i)*DPROJ;
  size_t yb = (size_t)(b*LL+l0+i)*DIN + h*HD + ps;
  #pragma unroll
  for (int pp=0;pp<16;pp++){
    float x = g_proj[pb + DIN + h*HD + ps + pp];
    float z = g_proj[pb + h*HD + ps + pp];
    float y = g_y[yb+pp] + e*acc[pp] + dv*x;
    g_y[yb+pp] = y * (z * sigm_(z));
  }
}

extern "C" void kernel_launch(void* const* d_in, const int* in_sizes, int n_in,
                              void* d_out, int out_size) {
  const float* u        = (const float*)d_in[0];
  const float* W_in     = (const float*)d_in[1];
  const float* W_out    = (const float*)d_in[2];
  const float* dt_bias  = (const float*)d_in[3];
  const float* B_bias   = (const float*)d_in[4];
  const float* C_bias   = (const float*)d_in[5];
  const float* B_norm_w = (const float*)d_in[6];
  const float* C_norm_w = (const float*)d_in[7];
  const float* Dv       = (const float*)d_in[8];
  float* out = (float*)d_out;
  (void)in_sizes; (void)n_in; (void)out_size;

  float *proj, *y;
  cudaGetSymbolAddress((void**)&proj, g_proj);
  cudaGetSymbolAddress((void**)&y, g_y);

  cudaFuncSetAttribute(k_chunk, cudaFuncAttributeMaxDynamicSharedMemorySize, SMEM_CHUNK);
  cudaFuncSetAttribute(k_inter, cudaFuncAttributeMaxDynamicSharedMemorySize, SMEM_INTER);

  // 1. proj = u @ W_in : [4096,1024]x[1024,4480]
  sgemm128<<<dim3(DPROJ/128, (BB*LL)/128), 256>>>(u, W_in, proj, BB*LL, DPROJ, DM);
  // 2. dt / adt / g1 / g2
  k_point<<<(BB*LL*NH + 255)/256, 256>>>(dt_bias);
  // 3. theta cumsum
  k_theta<<<BB*NH, NA>>>();
  // 4. rmsnorm + rope -> Q, K
  k_qk<<<BB*LL, DS>>>(B_bias, C_bias, B_norm_w, C_norm_w);
  // 5. intra-chunk: S, y_intra, Wsum
  k_chunk<<<BB*NC*NH, 256, SMEM_CHUNK>>>();
  // 6. inter-chunk scan
  k_scan<<<BB*NH, 256>>>();
  // 7. y_inter + gating
  k_inter<<<BB*NC*NH, 256, SMEM_INTER>>>(Dv);
  // 8. out = y @ W_out : [4096,2048]x[2048,1024]
  sgemm128<<<dim3(DM/128, (BB*LL)/128), 256>>>(y, W_out, out, BB*LL, DM, DIN);
}

// round 5
// speedup vs baseline: 1.8862x; 1.8862x over previous
#include <cuda_runtime.h>
#include <math.h>

#define BB 2
#define LL 2048
#define DM 1024
#define DIN 2048
#define NH 32
#define HD 64
#define DS 128
#define NA 32
#define NC 32
#define CK 64
#define DPROJ 4480
#define EPSF 1e-5f

// ---- scratch (device globals; no allocation allowed) ----
__device__ __align__(256) float g_proj[(size_t)BB*LL*DPROJ];     // 73 MB
__device__ __align__(256) float g_Q[(size_t)BB*LL*NH*DS];        // 67 MB
__device__ __align__(256) float g_K[(size_t)BB*LL*NH*DS];        // 67 MB
__device__ __align__(256) float g_dt[BB*LL*NH];
__device__ __align__(256) float g_adt[BB*LL*NH];
__device__ __align__(256) float g_g1[BB*LL*NH];
__device__ __align__(256) float g_g2[BB*LL*NH];
__device__ __align__(256) float g_theta[(size_t)BB*LL*NH*NA];    // 17 MB
__device__ __align__(256) float g_eell[BB*LL*NH];
__device__ __align__(256) float g_cd[BB*NC*NH];
__device__ __align__(256) float g_W[(size_t)BB*NC*NH*HD*DS];     // 67 MB
__device__ __align__(256) float g_y[(size_t)BB*LL*DIN];          // 33 MB

__device__ __forceinline__ float sp_(float x){ return x > 20.f ? x : log1pf(expf(x)); }
__device__ __forceinline__ float sigm_(float x){ return 1.f/(1.f+expf(-x)); }

// ---------------- SGEMM: C[M,N] = A[M,K] @ B[K,N], all row-major ----------------
// (R3-proven, verbatim) BM=BN=128, BK=8, 256 threads, 8x8 per thread.
__global__ void __launch_bounds__(256) sgemm128(const float* __restrict__ A,
                                                const float* __restrict__ Bm,
                                                float* __restrict__ C,
                                                int M, int N, int K) {
  __shared__ float As[8][128];
  __shared__ float Bs[8][128];
  int t = threadIdx.x;
  int bx = blockIdx.x, by = blockIdx.y;
  int tx = t & 15, ty = t >> 4;
  int ar = t >> 1, ac = (t & 1) * 4;
  int br = t >> 5, bc = (t & 31) * 4;
  const float* Ap = A + (size_t)(by*128 + ar)*K + ac;
  const float* Bp = Bm + (size_t)br*N + bx*128 + bc;
  float acc[8][8];
  #pragma unroll
  for (int i=0;i<8;i++)
    #pragma unroll
    for (int j=0;j<8;j++) acc[i][j]=0.f;
  for (int k0=0;k0<K;k0+=8) {
    float4 a4 = *(const float4*)(Ap + k0);
    float4 b4 = *(const float4*)(Bp + (size_t)k0*N);
    As[ac+0][ar]=a4.x; As[ac+1][ar]=a4.y; As[ac+2][ar]=a4.z; As[ac+3][ar]=a4.w;
    *(float4*)&Bs[br][bc] = b4;
    __syncthreads();
    #pragma unroll
    for (int kk=0;kk<8;kk++){
      float a[8], b[8];
      *(float4*)(a)   = *(const float4*)&As[kk][ty*8];
      *(float4*)(a+4) = *(const float4*)&As[kk][ty*8+4];
      *(float4*)(b)   = *(const float4*)&Bs[kk][tx*8];
      *(float4*)(b+4) = *(const float4*)&Bs[kk][tx*8+4];
      #pragma unroll
      for (int i=0;i<8;i++)
        #pragma unroll
        for (int j=0;j<8;j++) acc[i][j] += a[i]*b[j];
    }
    __syncthreads();
  }
  #pragma unroll
  for (int i=0;i<8;i++){
    float* Cp = C + (size_t)(by*128 + ty*8 + i)*N + bx*128 + tx*8;
    *(float4*)Cp     = make_float4(acc[i][0],acc[i][1],acc[i][2],acc[i][3]);
    *(float4*)(Cp+4) = make_float4(acc[i][4],acc[i][5],acc[i][6],acc[i][7]);
  }
}

// ---------------- pointwise: dt, adt, g1, g2 ----------------
__global__ void k_point(const float* __restrict__ dt_bias) {
  int idx = blockIdx.x*256 + threadIdx.x;
  if (idx >= BB*LL*NH) return;
  int h = idx % NH; int bl = idx / NH; int l = bl % LL;
  size_t base = (size_t)bl * DPROJ;
  float db = dt_bias[h];
  float dt = sp_(g_proj[base + 4352 + h] + db);
  float a  = fminf(-sp_(g_proj[base + 4384 + h]), -1e-4f);
  float adt = a * dt;
  float beta = sigm_(g_proj[base + 4416 + h]);
  float dtp = (l > 0) ? sp_(g_proj[base - DPROJ + 4352 + h] + db) : 0.f;
  g_dt[idx]  = dt;
  g_adt[idx] = adt;
  g_g1[idx]  = beta * dt;
  g_g2[idx]  = (1.f - beta) * expf(adt) * dtp;
}

// ---------------- theta cumsum over L (parallel: segment sums + prefix + rescan) ----------------
__global__ void __launch_bounds__(1024) k_theta2() {
  int b = blockIdx.x / NH, h = blockIdx.x % NH;
  int t = threadIdx.x;
  int a = t & 31;      // angle
  int s = t >> 5;      // segment 0..31, each 64 tokens
  __shared__ float ss[32][33];
  const float* pang = g_proj + (size_t)b*LL*DPROJ + 4448 + a;
  const float* pdt  = g_dt  + (size_t)b*LL*NH + h;
  int l0 = s*64;
  float loc = 0.f;
  for (int l=l0; l<l0+64; l++)
    loc += pang[(size_t)l*DPROJ] * pdt[(size_t)l*NH];
  ss[s][a] = loc;
  __syncthreads();
  float run = 0.f;
  for (int sp=0; sp<s; sp++) run += ss[sp][a];
  for (int l=l0; l<l0+64; l++){
    run += pang[(size_t)l*DPROJ] * pdt[(size_t)l*NH];
    g_theta[((size_t)(b*LL + l)*NH + h)*NA + a] = run;
  }
}

// ---------------- RMSNorm + bias + RoPE -> Q, K ----------------
__global__ void __launch_bounds__(128) k_qk(const float* __restrict__ B_bias,
                                            const float* __restrict__ C_bias,
                                            const float* __restrict__ Bw,
                                            const float* __restrict__ Cw) {
  int bl = blockIdx.x;
  int p = threadIdx.x;
  __shared__ float Bn[DS], Cn[DS];
  __shared__ float rs[4][2];
  size_t base = (size_t)bl * DPROJ;
  float bg = g_proj[base + 4096 + p];
  float cg = g_proj[base + 4224 + p];
  float sb = bg*bg, sc = cg*cg;
  #pragma unroll
  for (int o=16;o>0;o>>=1){
    sb += __shfl_xor_sync(0xffffffff, sb, o);
    sc += __shfl_xor_sync(0xffffffff, sc, o);
  }
  if ((p&31)==0){ rs[p>>5][0]=sb; rs[p>>5][1]=sc; }
  __syncthreads();
  float tb = rs[0][0]+rs[1][0]+rs[2][0]+rs[3][0];
  float tc = rs[0][1]+rs[1][1]+rs[2][1]+rs[3][1];
  float rB = rsqrtf(tb/(float)DS + EPSF);
  float rC = rsqrtf(tc/(float)DS + EPSF);
  Bn[p] = bg*rB*Bw[p];
  Cn[p] = cg*rC*Cw[p];
  __syncthreads();
  const float* th = g_theta + (size_t)bl*NH*NA;
  for (int h=0; h<NH; h++){
    float outK, outQ;
    if (p < 64) {
      int a = p & 31;
      float ang = th[h*NA + a];
      float c = cosf(ang), s = sinf(ang);
      if (p < 32) {
        float k1 = Bn[p]    + B_bias[h*DS+p];
        float k2 = Bn[p+32] + B_bias[h*DS+p+32];
        outK = k1*c - k2*s;
        float q1 = Cn[p]    + C_bias[h*DS+p];
        float q2 = Cn[p+32] + C_bias[h*DS+p+32];
        outQ = q1*c - q2*s;
      } else {
        float k1 = Bn[a] + B_bias[h*DS+a];
        float k2 = Bn[p] + B_bias[h*DS+p];
        outK = k1*s + k2*c;
        float q1 = Cn[a] + C_bias[h*DS+a];
        float q2 = Cn[p] + C_bias[h*DS+p];
        outQ = q1*s + q2*c;
      }
    } else {
      outK = Bn[p] + B_bias[h*DS+p];
      outQ = Cn[p] + C_bias[h*DS+p];
    }
    size_t o = ((size_t)bl*NH + h)*DS + p;
    g_K[o] = outK;
    g_Q[o] = outQ;
  }
}

// ---------------- chunk kernel: S1/S2, y_intra, Wsum (512 threads) ----------------
#define QSS 129
#define SMEM_CHUNK ((64*QSS + 65*QSS + 65*64 + 64*64*2)*4)
__global__ void __launch_bounds__(512) k_chunk() {
  extern __shared__ float sm[];
  float* Qs = sm;                  // 64 x 129
  float* Ke = Qs + 64*QSS;         // 65 x 129 (row r = token l0+r-1)
  float* xe = Ke + 65*QSS;         // 65 x 64
  float* S1 = xe + 65*64;          // 64 x 64
  float* S2 = S1 + 64*64;          // 64 x 64
  __shared__ float ell[CK], g1s[CK], g2s[CK], w1s[CK], w2s[CK];
  int t = threadIdx.x;
  int bid = blockIdx.x;
  int h = bid % NH; int c = (bid/NH) % NC; int b = bid/(NH*NC);
  int l0 = c*CK;
  size_t qbase = ((size_t)(b*LL + l0)*NH + h)*DS;
  for (int idx=t; idx<64*DS; idx+=512){
    int i = idx >> 7, n = idx & 127;
    Qs[i*QSS+n] = g_Q[qbase + (size_t)i*NH*DS + n];
  }
  for (int idx=t; idx<65*DS; idx+=512){
    int r = idx >> 7, n = idx & 127;
    int l = l0 + r - 1;
    Ke[r*QSS+n] = (l >= 0) ? g_K[((size_t)(b*LL + l)*NH + h)*DS + n] : 0.f;
  }
  for (int idx=t; idx<65*HD; idx+=512){
    int r = idx >> 6, pp = idx & 63;
    int l = l0 + r - 1;
    xe[r*64+pp] = (l >= 0) ? g_proj[(size_t)(b*LL + l)*DPROJ + DIN + h*HD + pp] : 0.f;
  }
  if (t < CK) {
    int gi = (b*LL + l0 + t)*NH + h;
    g1s[t] = g_g1[gi]; g2s[t] = g_g2[gi];
    ell[t] = g_adt[gi];
  }
  __syncthreads();
  if (t == 0) {
    float run = 0.f;
    for (int j=0;j<CK;j++){ run += ell[j]; ell[j] = run; }
  }
  __syncthreads();
  if (t < CK) {
    float e63 = ell[CK-1];
    float de = expf(e63 - ell[t]);
    w1s[t] = g1s[t]*de; w2s[t] = g2s[t]*de;
    g_eell[(b*LL + l0 + t)*NH + h] = expf(ell[t]);
    if (t == 0) g_cd[bid] = expf(e63);
  }
  __syncthreads();
  // Phase A: S1[i][j], S2[i][j]  (thread: i = t>>3, 8 consecutive j)
  {
    int i = t >> 3;
    int js = (t & 7) * 8;
    float a1[8], a2[8];
    #pragma unroll
    for (int jj=0;jj<8;jj++){ a1[jj]=0.f; a2[jj]=0.f; }
    for (int n=0;n<DS;n++){
      float q = Qs[i*QSS+n];
      float kv[9];
      #pragma unroll
      for (int r=0;r<9;r++) kv[r] = Ke[(js+r)*QSS+n];
      #pragma unroll
      for (int jj=0;jj<8;jj++){
        a1[jj] += q*kv[jj+1];
        a2[jj] += q*kv[jj];
      }
    }
    float ei = ell[i];
    #pragma unroll
    for (int jj=0;jj<8;jj++){
      int j = js + jj;
      float d = (j <= i) ? expf(ei - ell[j]) : 0.f;
      S1[i*64+j] = a1[jj]*g1s[j]*d;
      S2[i*64+j] = a2[jj]*g2s[j]*d;
    }
  }
  __syncthreads();
  // Phase B: y_intra -> g_y  (thread: i = t>>3, p = (t&7) + 8*pp : conflict-free + coalesced)
  {
    int i = t >> 3;
    int pb = t & 7;
    float acc[8];
    #pragma unroll
    for (int pp=0;pp<8;pp++) acc[pp]=0.f;
    for (int j=0;j<=i;j++){
      float s1 = S1[i*64+j], s2 = S2[i*64+j];
      #pragma unroll
      for (int pp=0;pp<8;pp++){
        int p = pb + pp*8;
        acc[pp] += s1*xe[(j+1)*64+p] + s2*xe[j*64+p];
      }
    }
    size_t yb = (size_t)(b*LL + l0 + i)*DIN + h*HD + pb;
    #pragma unroll
    for (int pp=0;pp<8;pp++) g_y[yb + pp*8] = acc[pp];
  }
  // Phase C: Wsum[p][n] -> g_W  (thread: p = t>>3, n = (t&7) + 8*nn)
  {
    int p = t >> 3;
    int nb = t & 7;
    float acc[16];
    #pragma unroll
    for (int nn=0;nn<16;nn++) acc[nn]=0.f;
    for (int j=0;j<CK;j++){
      float a1 = w1s[j]*xe[(j+1)*64+p];
      float a2 = w2s[j]*xe[j*64+p];
      #pragma unroll
      for (int nn=0;nn<16;nn++){
        int n = nb + nn*8;
        acc[nn] += a1*Ke[(j+1)*QSS+n] + a2*Ke[j*QSS+n];
      }
    }
    size_t wb = ((size_t)bid*HD + p)*DS + nb;
    #pragma unroll
    for (int nn=0;nn<16;nn++) g_W[wb + nn*8] = acc[nn];
  }
}

// ---------------- inter-chunk state scan (in place: Wsum -> Hprev), 256 blocks ----------------
__global__ void __launch_bounds__(256) k_scan2() {
  int blk = blockIdx.x;
  int bh = blk >> 2, part = blk & 3;
  int b = bh / NH, h = bh % NH;
  int e0 = part*2048 + threadIdx.x*8;
  float H[8];
  #pragma unroll
  for (int r=0;r<8;r++) H[r]=0.f;
  for (int c=0;c<NC;c++){
    int bid = (b*NC + c)*NH + h;
    float cd = g_cd[bid];
    float* p = g_W + (size_t)bid*(HD*DS) + e0;
    float4 w0 = *(float4*)p;
    float4 w1 = *(float4*)(p+4);
    *(float4*)p     = make_float4(H[0],H[1],H[2],H[3]);
    *(float4*)(p+4) = make_float4(H[4],H[5],H[6],H[7]);
    H[0]=cd*H[0]+w0.x; H[1]=cd*H[1]+w0.y; H[2]=cd*H[2]+w0.z; H[3]=cd*H[3]+w0.w;
    H[4]=cd*H[4]+w1.x; H[5]=cd*H[5]+w1.y; H[6]=cd*H[6]+w1.z; H[7]=cd*H[7]+w1.w;
  }
}

// ---------------- y_inter + D*x + SiLU gating ----------------
#define SMEM_INTER ((64*QSS*2)*4)
__global__ void __launch_bounds__(256) k_inter(const float* __restrict__ Dp) {
  extern __shared__ float sm[];
  float* Hs = sm;             // 64(p) x 129(n)
  float* Qs = Hs + 64*QSS;    // 64(i) x 129(n)
  __shared__ float eel[CK];
  int t = threadIdx.x;
  int bid = blockIdx.x;
  int h = bid % NH; int c = (bid/NH)%NC; int b = bid/(NH*NC);
  int l0 = c*CK;
  size_t wbase = (size_t)bid*HD*DS;
  for (int idx=t; idx<HD*DS; idx+=256){
    int p = idx>>7, n = idx&127;
    Hs[p*QSS+n] = g_W[wbase + idx];
  }
  size_t qbase = ((size_t)(b*LL+l0)*NH + h)*DS;
  for (int idx=t; idx<CK*DS; idx+=256){
    int i = idx>>7, n = idx&127;
    Qs[i*QSS+n] = g_Q[qbase + (size_t)i*NH*DS + n];
  }
  if (t < CK) eel[t] = g_eell[(b*LL+l0+t)*NH + h];
  __syncthreads();
  int i = t>>2, ps = (t&3)*16;
  float acc[16];
  #pragma unroll
  for (int pp=0;pp<16;pp++) acc[pp]=0.f;
  for (int n=0;n<DS;n++){
    float q = Qs[i*QSS+n];
    #pragma unroll
    for (int pp=0;pp<16;pp++) acc[pp] += q*Hs[(ps+pp)*QSS+n];
  }
  float e = eel[i];
  float dv = Dp[h];
  size_t pb = (size_t)(b*LL+l0+i)*DPROJ;
  size_t yb = (size_t)(b*LL+l0+i)*DIN + h*HD + ps;
  #pragma unroll
  for (int pp=0;pp<16;pp++){
    float x = g_proj[pb + DIN + h*HD + ps + pp];
    float z = g_proj[pb + h*HD + ps + pp];
    float y = g_y[yb+pp] + e*acc[pp] + dv*x;
    g_y[yb+pp] = y * (z * sigm_(z));
  }
}

extern "C" void kernel_launch(void* const* d_in, const int* in_sizes, int n_in,
                              void* d_out, int out_size) {
  const float* u        = (const float*)d_in[0];
  const float* W_in     = (const float*)d_in[1];
  const float* W_out    = (const float*)d_in[2];
  const float* dt_bias  = (const float*)d_in[3];
  const float* B_bias   = (const float*)d_in[4];
  const float* C_bias   = (const float*)d_in[5];
  const float* B_norm_w = (const float*)d_in[6];
  const float* C_norm_w = (const float*)d_in[7];
  const float* Dv       = (const float*)d_in[8];
  float* out = (float*)d_out;
  (void)in_sizes; (void)n_in; (void)out_size;

  float *proj, *y;
  cudaGetSymbolAddress((void**)&proj, g_proj);
  cudaGetSymbolAddress((void**)&y, g_y);

  cudaFuncSetAttribute(k_chunk, cudaFuncAttributeMaxDynamicSharedMemorySize, SMEM_CHUNK);
  cudaFuncSetAttribute(k_inter, cudaFuncAttributeMaxDynamicSharedMemorySize, SMEM_INTER);

  // 1. proj = u @ W_in : [4096,1024]x[1024,4480]  (R3-proven fp32 GEMM)
  sgemm128<<<dim3(DPROJ/128, (BB*LL)/128), 256>>>(u, W_in, proj, BB*LL, DPROJ, DM);
  // 2. dt / adt / g1 / g2
  k_point<<<(BB*LL*NH + 255)/256, 256>>>(dt_bias);
  // 3. theta cumsum (parallel scan)
  k_theta2<<<BB*NH, 1024>>>();
  // 4. rmsnorm + rope -> Q, K
  k_qk<<<BB*LL, DS>>>(B_bias, C_bias, B_norm_w, C_norm_w);
  // 5. intra-chunk: S, y_intra, Wsum
  k_chunk<<<BB*NC*NH, 512, SMEM_CHUNK>>>();
  // 6. inter-chunk scan
  k_scan2<<<BB*NH*4, 256>>>();
  // 7. y_inter + gating
  k_inter<<<BB*NC*NH, 256, SMEM_INTER>>>(Dv);
  // 8. out = y @ W_out : [4096,2048]x[2048,1024]
  sgemm128<<<dim3(DM/128, (BB*LL)/128), 256>>>(y, W_out, out, BB*LL, DM, DIN);
}

// round 8
// speedup vs baseline: 2.6937x; 1.4281x over previous
#include <cuda_runtime.h>
#include <cuda_bf16.h>
#include <math.h>

#define BB 2
#define LL 2048
#define DM 1024
#define DIN 2048
#define NH 32
#define HD 64
#define DS 128
#define NA 32
#define NC 32
#define CK 64
#define DPROJ 4480
#define EPSF 1e-5f

// ---- scratch (device globals; no allocation allowed) ----
__device__ __align__(256) float g_proj[(size_t)BB*LL*DPROJ];     // 73 MB
__device__ __align__(256) float g_Q[(size_t)BB*LL*NH*DS];        // 67 MB
__device__ __align__(256) float g_K[(size_t)BB*LL*NH*DS];        // 67 MB
__device__ __align__(256) float g_dt[BB*LL*NH];
__device__ __align__(256) float g_adt[BB*LL*NH];
__device__ __align__(256) float g_g1[BB*LL*NH];
__device__ __align__(256) float g_g2[BB*LL*NH];
__device__ __align__(256) float g_theta[(size_t)BB*LL*NH*NA];    // 17 MB
__device__ __align__(256) float g_eell[BB*LL*NH];
__device__ __align__(256) float g_cd[BB*NC*NH];
__device__ __align__(256) float g_W[(size_t)BB*NC*NH*HD*DS];     // 67 MB
__device__ __align__(256) float g_y[(size_t)BB*LL*DIN];          // 33 MB

__device__ __forceinline__ float sp_(float x){ return x > 20.f ? x : log1pf(expf(x)); }
__device__ __forceinline__ float sigm_(float x){ return 1.f/(1.f+expf(-x)); }

// ---------------- bf16-split tensor-core GEMM (raw mma.sync PTX) ----------------
// C[M,N] fp32 = A[M,K] @ B[K,N], row-major. Split A,B into hi/lo bf16 planes in
// smem; accumulate Ahi*Bhi + Ahi*Blo + Alo*Bhi in fp32 (drops ~2^-16 Al*Bl term).
// Block 128x128xK32, 256 threads = 8 warps (2x4), warp tile 64x32.
#define APAD 20    // uint32 row stride, A planes: [128 rows][16 k-pairs used]
#define BPAD 136   // uint32 row stride, B planes: [16 k-pairs][128 n used]

__device__ __forceinline__ unsigned pk_hi(float x, float y){
  __nv_bfloat162 h = __floats2bfloat162_rn(x, y);   // .x = x (low 16), .y = y
  return *(unsigned*)&h;
}
__device__ __forceinline__ unsigned pk_lo(float x, float y){
  float hx = __bfloat162float(__float2bfloat16(x));
  float hy = __bfloat162float(__float2bfloat16(y));
  __nv_bfloat162 h = __floats2bfloat162_rn(x - hx, y - hy);
  return *(unsigned*)&h;
}
__device__ __forceinline__ void mma16816(float* c, const unsigned* a, unsigned b0, unsigned b1){
  asm volatile("mma.sync.aligned.m16n8k16.row.col.f32.bf16.bf16.f32 "
      "{%0,%1,%2,%3}, {%4,%5,%6,%7}, {%8,%9}, {%0,%1,%2,%3};\n"
      : "+f"(c[0]), "+f"(c[1]), "+f"(c[2]), "+f"(c[3])
      : "r"(a[0]), "r"(a[1]), "r"(a[2]), "r"(a[3]), "r"(b0), "r"(b1));
}

__global__ void __launch_bounds__(256, 2) gemm_mma(const float* __restrict__ A,
                                                   const float* __restrict__ Bm,
                                                   float* __restrict__ C,
                                                   int M, int N, int K) {
  __shared__ unsigned Ah[128*APAD];
  __shared__ unsigned Al[128*APAD];
  __shared__ unsigned Bh[16*BPAD];
  __shared__ unsigned Bl[16*BPAD];
  int t = threadIdx.x;
  int lane = t & 31, wid = t >> 5;
  int g = lane >> 2, tg = lane & 3;
  int wm = (wid >> 2) * 64;          // 0 or 64
  int wn = (wid & 3) * 32;           // 0..96
  int bx = blockIdx.x, by = blockIdx.y;

  float acc[4][4][4];
  #pragma unroll
  for (int i=0;i<4;i++)
    #pragma unroll
    for (int j=0;j<4;j++)
      #pragma unroll
      for (int r=0;r<4;r++) acc[i][j][r] = 0.f;

  // A loader: row = t>>1 (0..127), 16 consecutive k-cols at (t&1)*16
  int arow = t >> 1, ahalf = (t & 1) * 16;
  const float* Aptr = A + (size_t)(by*128 + arow)*K + ahalf;
  // B loader: k-pair = t>>4 (0..15), 8 consecutive n-cols at (t&15)*8
  int bkp = t >> 4, bcb = (t & 15) * 8;
  const float* Bptr0 = Bm + (size_t)(2*bkp)*N + bx*128 + bcb;
  const float* Bptr1 = Bptr0 + N;

  for (int k0 = 0; k0 < K; k0 += 32) {
    __syncthreads();
    // stage + split A tile: 128x32 fp32 -> Ah/Al (k-pair packed along k)
    #pragma unroll
    for (int q = 0; q < 4; q++) {
      float4 v = *(const float4*)(Aptr + k0 + q*4);
      int pi = (ahalf >> 1) + q*2;
      uint2 hv = make_uint2(pk_hi(v.x, v.y), pk_hi(v.z, v.w));
      uint2 lv = make_uint2(pk_lo(v.x, v.y), pk_lo(v.z, v.w));
      *(uint2*)&Ah[arow*APAD + pi] = hv;
      *(uint2*)&Al[arow*APAD + pi] = lv;
    }
    // stage + split B tile: 32x128 fp32 -> Bh/Bl ([kpair][n], pair packed along k)
    #pragma unroll
    for (int q = 0; q < 2; q++) {
      float4 r0 = *(const float4*)(Bptr0 + (size_t)k0*N + q*4);
      float4 r1 = *(const float4*)(Bptr1 + (size_t)k0*N + q*4);
      int nb = bcb + q*4;
      uint4 hv = make_uint4(pk_hi(r0.x, r1.x), pk_hi(r0.y, r1.y),
                            pk_hi(r0.z, r1.z), pk_hi(r0.w, r1.w));
      uint4 lv = make_uint4(pk_lo(r0.x, r1.x), pk_lo(r0.y, r1.y),
                            pk_lo(r0.z, r1.z), pk_lo(r0.w, r1.w));
      *(uint4*)&Bh[bkp*BPAD + nb] = hv;
      *(uint4*)&Bl[bkp*BPAD + nb] = lv;
    }
    __syncthreads();
    // compute: 2 x k16 steps
    #pragma unroll
    for (int ks = 0; ks < 2; ks++) {
      unsigned afh[4][4], afl[4][4];
      #pragma unroll
      for (int i = 0; i < 4; i++) {
        int r0 = wm + i*16 + g;
        int c0 = ks*8 + tg;
        afh[i][0] = Ah[r0*APAD + c0];
        afh[i][1] = Ah[(r0+8)*APAD + c0];
        afh[i][2] = Ah[r0*APAD + c0 + 4];
        afh[i][3] = Ah[(r0+8)*APAD + c0 + 4];
        afl[i][0] = Al[r0*APAD + c0];
        afl[i][1] = Al[(r0+8)*APAD + c0];
        afl[i][2] = Al[r0*APAD + c0 + 4];
        afl[i][3] = Al[(r0+8)*APAD + c0 + 4];
      }
      #pragma unroll
      for (int j = 0; j < 4; j++) {
        int nn = wn + j*8 + g;
        int kp = ks*8 + tg;
        unsigned bh0 = Bh[kp*BPAD + nn], bh1 = Bh[(kp+4)*BPAD + nn];
        unsigned bl0 = Bl[kp*BPAD + nn], bl1 = Bl[(kp+4)*BPAD + nn];
        #pragma unroll
        for (int i = 0; i < 4; i++) {
          mma16816(acc[i][j], afh[i], bh0, bh1);
          mma16816(acc[i][j], afh[i], bl0, bl1);
          mma16816(acc[i][j], afl[i], bh0, bh1);
        }
      }
    }
  }
  // epilogue
  #pragma unroll
  for (int i = 0; i < 4; i++) {
    int row = by*128 + wm + i*16 + g;
    #pragma unroll
    for (int j = 0; j < 4; j++) {
      int col = bx*128 + wn + j*8 + tg*2;
      *(float2*)&C[(size_t)row*N + col]     = make_float2(acc[i][j][0], acc[i][j][1]);
      *(float2*)&C[(size_t)(row+8)*N + col] = make_float2(acc[i][j][2], acc[i][j][3]);
    }
  }
}

// ---------------- pointwise: dt, adt, g1, g2 ----------------
__global__ void k_point(const float* __restrict__ dt_bias) {
  int idx = blockIdx.x*256 + threadIdx.x;
  if (idx >= BB*LL*NH) return;
  int h = idx % NH; int bl = idx / NH; int l = bl % LL;
  size_t base = (size_t)bl * DPROJ;
  float db = dt_bias[h];
  float dt = sp_(g_proj[base + 4352 + h] + db);
  float a  = fminf(-sp_(g_proj[base + 4384 + h]), -1e-4f);
  float adt = a * dt;
  float beta = sigm_(g_proj[base + 4416 + h]);
  float dtp = (l > 0) ? sp_(g_proj[base - DPROJ + 4352 + h] + db) : 0.f;
  g_dt[idx]  = dt;
  g_adt[idx] = adt;
  g_g1[idx]  = beta * dt;
  g_g2[idx]  = (1.f - beta) * expf(adt) * dtp;
}

// ---------------- theta cumsum over L (parallel: segment sums + prefix + rescan) ----------------
__global__ void __launch_bounds__(1024) k_theta2() {
  int b = blockIdx.x / NH, h = blockIdx.x % NH;
  int t = threadIdx.x;
  int a = t & 31;      // angle
  int s = t >> 5;      // segment 0..31, each 64 tokens
  __shared__ float ss[32][33];
  const float* pang = g_proj + (size_t)b*LL*DPROJ + 4448 + a;
  const float* pdt  = g_dt  + (size_t)b*LL*NH + h;
  int l0 = s*64;
  float loc = 0.f;
  for (int l=l0; l<l0+64; l++)
    loc += pang[(size_t)l*DPROJ] * pdt[(size_t)l*NH];
  ss[s][a] = loc;
  __syncthreads();
  float run = 0.f;
  for (int sp=0; sp<s; sp++) run += ss[sp][a];
  for (int l=l0; l<l0+64; l++){
    run += pang[(size_t)l*DPROJ] * pdt[(size_t)l*NH];
    g_theta[((size_t)(b*LL + l)*NH + h)*NA + a] = run;
  }
}

// ---------------- RMSNorm + bias + RoPE -> Q, K ----------------
__global__ void __launch_bounds__(128) k_qk(const float* __restrict__ B_bias,
                                            const float* __restrict__ C_bias,
                                            const float* __restrict__ Bw,
                                            const float* __restrict__ Cw) {
  int bl = blockIdx.x;
  int p = threadIdx.x;
  __shared__ float Bn[DS], Cn[DS];
  __shared__ float rs[4][2];
  size_t base = (size_t)bl * DPROJ;
  float bg = g_proj[base + 4096 + p];
  float cg = g_proj[base + 4224 + p];
  float sb = bg*bg, sc = cg*cg;
  #pragma unroll
  for (int o=16;o>0;o>>=1){
    sb += __shfl_xor_sync(0xffffffff, sb, o);
    sc += __shfl_xor_sync(0xffffffff, sc, o);
  }
  if ((p&31)==0){ rs[p>>5][0]=sb; rs[p>>5][1]=sc; }
  __syncthreads();
  float tb = rs[0][0]+rs[1][0]+rs[2][0]+rs[3][0];
  float tc = rs[0][1]+rs[1][1]+rs[2][1]+rs[3][1];
  float rB = rsqrtf(tb/(float)DS + EPSF);
  float rC = rsqrtf(tc/(float)DS + EPSF);
  Bn[p] = bg*rB*Bw[p];
  Cn[p] = cg*rC*Cw[p];
  __syncthreads();
  const float* th = g_theta + (size_t)bl*NH*NA;
  for (int h=0; h<NH; h++){
    float outK, outQ;
    if (p < 64) {
      int a = p & 31;
      float ang = th[h*NA + a];
      float c = cosf(ang), s = sinf(ang);
      if (p < 32) {
        float k1 = Bn[p]    + B_bias[h*DS+p];
        float k2 = Bn[p+32] + B_bias[h*DS+p+32];
        outK = k1*c - k2*s;
        float q1 = Cn[p]    + C_bias[h*DS+p];
        float q2 = Cn[p+32] + C_bias[h*DS+p+32];
        outQ = q1*c - q2*s;
      } else {
        float k1 = Bn[a] + B_bias[h*DS+a];
        float k2 = Bn[p] + B_bias[h*DS+p];
        outK = k1*s + k2*c;
        float q1 = Cn[a] + C_bias[h*DS+a];
        float q2 = Cn[p] + C_bias[h*DS+p];
        outQ = q1*s + q2*c;
      }
    } else {
      outK = Bn[p] + B_bias[h*DS+p];
      outQ = Cn[p] + C_bias[h*DS+p];
    }
    size_t o = ((size_t)bl*NH + h)*DS + p;
    g_K[o] = outK;
    g_Q[o] = outQ;
  }
}

// ---------------- chunk kernel: S1/S2, y_intra, Wsum (512 threads) ----------------
#define QSS 129
#define SMEM_CHUNK ((64*QSS + 65*QSS + 65*64 + 64*64*2)*4)
__global__ void __launch_bounds__(512) k_chunk() {
  extern __shared__ float sm[];
  float* Qs = sm;                  // 64 x 129
  float* Ke = Qs + 64*QSS;         // 65 x 129 (row r = token l0+r-1)
  float* xe = Ke + 65*QSS;         // 65 x 64
  float* S1 = xe + 65*64;          // 64 x 64
  float* S2 = S1 + 64*64;          // 64 x 64
  __shared__ float ell[CK], g1s[CK], g2s[CK], w1s[CK], w2s[CK];
  int t = threadIdx.x;
  int bid = blockIdx.x;
  int h = bid % NH; int c = (bid/NH) % NC; int b = bid/(NH*NC);
  int l0 = c*CK;
  size_t qbase = ((size_t)(b*LL + l0)*NH + h)*DS;
  for (int idx=t; idx<64*DS; idx+=512){
    int i = idx >> 7, n = idx & 127;
    Qs[i*QSS+n] = g_Q[qbase + (size_t)i*NH*DS + n];
  }
  for (int idx=t; idx<65*DS; idx+=512){
    int r = idx >> 7, n = idx & 127;
    int l = l0 + r - 1;
    Ke[r*QSS+n] = (l >= 0) ? g_K[((size_t)(b*LL + l)*NH + h)*DS + n] : 0.f;
  }
  for (int idx=t; idx<65*HD; idx+=512){
    int r = idx >> 6, pp = idx & 63;
    int l = l0 + r - 1;
    xe[r*64+pp] = (l >= 0) ? g_proj[(size_t)(b*LL + l)*DPROJ + DIN + h*HD + pp] : 0.f;
  }
  if (t < CK) {
    int gi = (b*LL + l0 + t)*NH + h;
    g1s[t] = g_g1[gi]; g2s[t] = g_g2[gi];
    ell[t] = g_adt[gi];
  }
  __syncthreads();
  if (t == 0) {
    float run = 0.f;
    for (int j=0;j<CK;j++){ run += ell[j]; ell[j] = run; }
  }
  __syncthreads();
  if (t < CK) {
    float e63 = ell[CK-1];
    float de = expf(e63 - ell[t]);
    w1s[t] = g1s[t]*de; w2s[t] = g2s[t]*de;
    g_eell[(b*LL + l0 + t)*NH + h] = expf(ell[t]);
    if (t == 0) g_cd[bid] = expf(e63);
  }
  __syncthreads();
  // Phase A: S1[i][j], S2[i][j]  (thread: i = t>>3, 8 consecutive j)
  {
    int i = t >> 3;
    int js = (t & 7) * 8;
    float a1[8], a2[8];
    #pragma unroll
    for (int jj=0;jj<8;jj++){ a1[jj]=0.f; a2[jj]=0.f; }
    for (int n=0;n<DS;n++){
      float q = Qs[i*QSS+n];
      float kv[9];
      #pragma unroll
      for (int r=0;r<9;r++) kv[r] = Ke[(js+r)*QSS+n];
      #pragma unroll
      for (int jj=0;jj<8;jj++){
        a1[jj] += q*kv[jj+1];
        a2[jj] += q*kv[jj];
      }
    }
    float ei = ell[i];
    #pragma unroll
    for (int jj=0;jj<8;jj++){
      int j = js + jj;
      float d = (j <= i) ? expf(ei - ell[j]) : 0.f;
      S1[i*64+j] = a1[jj]*g1s[j]*d;
      S2[i*64+j] = a2[jj]*g2s[j]*d;
    }
  }
  __syncthreads();
  // Phase B: y_intra -> g_y  (thread: i = t>>3, p = (t&7) + 8*pp : conflict-free + coalesced)
  {
    int i = t >> 3;
    int pb = t & 7;
    float acc[8];
    #pragma unroll
    for (int pp=0;pp<8;pp++) acc[pp]=0.f;
    for (int j=0;j<=i;j++){
      float s1 = S1[i*64+j], s2 = S2[i*64+j];
      #pragma unroll
      for (int pp=0;pp<8;pp++){
        int p = pb + pp*8;
        acc[pp] += s1*xe[(j+1)*64+p] + s2*xe[j*64+p];
      }
    }
    size_t yb = (size_t)(b*LL + l0 + i)*DIN + h*HD + pb;
    #pragma unroll
    for (int pp=0;pp<8;pp++) g_y[yb + pp*8] = acc[pp];
  }
  // Phase C: Wsum[p][n] -> g_W  (thread: p = t>>3, n = (t&7) + 8*nn)
  {
    int p = t >> 3;
    int nb = t & 7;
    float acc[16];
    #pragma unroll
    for (int nn=0;nn<16;nn++) acc[nn]=0.f;
    for (int j=0;j<CK;j++){
      float a1 = w1s[j]*xe[(j+1)*64+p];
      float a2 = w2s[j]*xe[j*64+p];
      #pragma unroll
      for (int nn=0;nn<16;nn++){
        int n = nb + nn*8;
        acc[nn] += a1*Ke[(j+1)*QSS+n] + a2*Ke[j*QSS+n];
      }
    }
    size_t wb = ((size_t)bid*HD + p)*DS + nb;
    #pragma unroll
    for (int nn=0;nn<16;nn++) g_W[wb + nn*8] = acc[nn];
  }
}

// ---------------- inter-chunk state scan (in place: Wsum -> Hprev), 256 blocks ----------------
__global__ void __launch_bounds__(256) k_scan2() {
  int blk = blockIdx.x;
  int bh = blk >> 2, part = blk & 3;
  int b = bh / NH, h = bh % NH;
  int e0 = part*2048 + threadIdx.x*8;
  float H[8];
  #pragma unroll
  for (int r=0;r<8;r++) H[r]=0.f;
  for (int c=0;c<NC;c++){
    int bid = (b*NC + c)*NH + h;
    float cd = g_cd[bid];
    float* p = g_W + (size_t)bid*(HD*DS) + e0;
    float4 w0 = *(float4*)p;
    float4 w1 = *(float4*)(p+4);
    *(float4*)p     = make_float4(H[0],H[1],H[2],H[3]);
    *(float4*)(p+4) = make_float4(H[4],H[5],H[6],H[7]);
    H[0]=cd*H[0]+w0.x; H[1]=cd*H[1]+w0.y; H[2]=cd*H[2]+w0.z; H[3]=cd*H[3]+w0.w;
    H[4]=cd*H[4]+w1.x; H[5]=cd*H[5]+w1.y; H[6]=cd*H[6]+w1.z; H[7]=cd*H[7]+w1.w;
  }
}

// ---------------- y_inter + D*x + SiLU gating ----------------
#define SMEM_INTER ((64*QSS*2)*4)
__global__ void __launch_bounds__(256) k_inter(const float* __restrict__ Dp) {
  extern __shared__ float sm[];
  float* Hs = sm;             // 64(p) x 129(n)
  float* Qs = Hs + 64*QSS;    // 64(i) x 129(n)
  __shared__ float eel[CK];
  int t = threadIdx.x;
  int bid = blockIdx.x;
  int h = bid % NH; int c = (bid/NH)%NC; int b = bid/(NH*NC);
  int l0 = c*CK;
  size_t wbase = (size_t)bid*HD*DS;
  for (int idx=t; idx<HD*DS; idx+=256){
    int p = idx>>7, n = idx&127;
    Hs[p*QSS+n] = g_W[wbase + idx];
  }
  size_t qbase = ((size_t)(b*LL+l0)*NH + h)*DS;
  for (int idx=t; idx<CK*DS; idx+=256){
    int i = idx>>7, n = idx&127;
    Qs[i*QSS+n] = g_Q[qbase + (size_t)i*NH*DS + n];
  }
  if (t < CK) eel[t] = g_eell[(b*LL+l0+t)*NH + h];
  __syncthreads();
  int i = t>>2, ps = (t&3)*16;
  float acc[16];
  #pragma unroll
  for (int pp=0;pp<16;pp++) acc[pp]=0.f;
  for (int n=0;n<DS;n++){
    float q = Qs[i*QSS+n];
    #pragma unroll
    for (int pp=0;pp<16;pp++) acc[pp] += q*Hs[(ps+pp)*QSS+n];
  }
  float e = eel[i];
  float dv = Dp[h];
  size_t pb = (size_t)(b*LL+l0+i)*DPROJ;
  size_t yb = (size_t)(b*LL+l0+i)*DIN + h*HD + ps;
  #pragma unroll
  for (int pp=0;pp<16;pp++){
    float x = g_proj[pb + DIN + h*HD + ps + pp];
    float z = g_proj[pb + h*HD + ps + pp];
    float y = g_y[yb+pp] + e*acc[pp] + dv*x;
    g_y[yb+pp] = y * (z * sigm_(z));
  }
}

extern "C" void kernel_launch(void* const* d_in, const int* in_sizes, int n_in,
                              void* d_out, int out_size) {
  const float* u        = (const float*)d_in[0];
  const float* W_in     = (const float*)d_in[1];
  const float* W_out    = (const float*)d_in[2];
  const float* dt_bias  = (const float*)d_in[3];
  const float* B_bias   = (const float*)d_in[4];
  const float* C_bias   = (const float*)d_in[5];
  const float* B_norm_w = (const float*)d_in[6];
  const float* C_norm_w = (const float*)d_in[7];
  const float* Dv       = (const float*)d_in[8];
  float* out = (float*)d_out;
  (void)in_sizes; (void)n_in; (void)out_size;

  float *proj, *y;
  cudaGetSymbolAddress((void**)&proj, g_proj);
  cudaGetSymbolAddress((void**)&y, g_y);

  cudaFuncSetAttribute(k_chunk, cudaFuncAttributeMaxDynamicSharedMemorySize, SMEM_CHUNK);
  cudaFuncSetAttribute(k_inter, cudaFuncAttributeMaxDynamicSharedMemorySize, SMEM_INTER);

  // 1. proj = u @ W_in : [4096,1024]x[1024,4480]  (bf16-split mma.sync GEMM)
  gemm_mma<<<dim3(DPROJ/128, (BB*LL)/128), 256>>>(u, W_in, proj, BB*LL, DPROJ, DM);
  // 2. dt / adt / g1 / g2
  k_point<<<(BB*LL*NH + 255)/256, 256>>>(dt_bias);
  // 3. theta cumsum (parallel scan)
  k_theta2<<<BB*NH, 1024>>>();
  // 4. rmsnorm + rope -> Q, K
  k_qk<<<BB*LL, DS>>>(B_bias, C_bias, B_norm_w, C_norm_w);
  // 5. intra-chunk: S, y_intra, Wsum
  k_chunk<<<BB*NC*NH, 512, SMEM_CHUNK>>>();
  // 6. inter-chunk scan
  k_scan2<<<BB*NH*4, 256>>>();
  // 7. y_inter + gating
  k_inter<<<BB*NC*NH, 256, SMEM_INTER>>>(Dv);
  // 8. out = y @ W_out : [4096,2048]x[2048,1024]  (bf16-split mma.sync GEMM)
  gemm_mma<<<dim3(DM/128, (BB*LL)/128), 256>>>(y, W_out, out, BB*LL, DM, DIN);
}

// round 14
// speedup vs baseline: 2.9835x; 1.1076x over previous
#include <cuda_runtime.h>
#include <cuda_bf16.h>
#include <math.h>

#define BB 2
#define LL 2048
#define DM 1024
#define DIN 2048
#define NH 32
#define HD 64
#define DS 128
#define NA 32
#define NC 32
#define CK 64
#define DPROJ 4480
#define EPSF 1e-5f

// ---- scratch (device globals; no allocation allowed) ----
__device__ __align__(256) float g_proj[(size_t)BB*LL*DPROJ];     // 73 MB
__device__ __align__(256) float g_Q[(size_t)BB*LL*NH*DS];        // 67 MB
__device__ __align__(256) float g_K[(size_t)BB*LL*NH*DS];        // 67 MB
__device__ __align__(256) float g_dt[BB*LL*NH];
__device__ __align__(256) float g_adt[BB*LL*NH];
__device__ __align__(256) float g_g1[BB*LL*NH];
__device__ __align__(256) float g_g2[BB*LL*NH];
__device__ __align__(256) float g_theta[(size_t)BB*LL*NH*NA];    // 17 MB
__device__ __align__(256) float g_eell[BB*LL*NH];
__device__ __align__(256) float g_cd[BB*NC*NH];
__device__ __align__(256) float g_W[(size_t)BB*NC*NH*HD*DS];     // 67 MB
__device__ __align__(256) float g_y[(size_t)BB*LL*DIN];          // 33 MB

__device__ __forceinline__ float sp_(float x){ return x > 20.f ? x : log1pf(expf(x)); }
__device__ __forceinline__ float sigm_(float x){ return 1.f/(1.f+expf(-x)); }

// ---------------- bf16-split tensor-core GEMM (raw mma.sync PTX) ----------------
// C[M,N] fp32 = A[M,K] @ B[K,N], row-major. Split A,B into hi/lo bf16 planes in
// smem; accumulate Ahi*Bhi + Ahi*Blo + Alo*Bhi in fp32 (drops ~2^-16 Al*Bl term).
// Block 128x128xK32, 256 threads = 8 warps (2x4), warp tile 64x32.
#define APAD 20    // uint32 row stride, A planes: [128 rows][16 k-pairs used]
#define BPAD 136   // uint32 row stride, B planes: [16 k-pairs][128 n used]

__device__ __forceinline__ unsigned pk_hi(float x, float y){
  __nv_bfloat162 h = __floats2bfloat162_rn(x, y);   // .x = x (low 16), .y = y
  return *(unsigned*)&h;
}
__device__ __forceinline__ unsigned pk_lo(float x, float y){
  float hx = __bfloat162float(__float2bfloat16(x));
  float hy = __bfloat162float(__float2bfloat16(y));
  __nv_bfloat162 h = __floats2bfloat162_rn(x - hx, y - hy);
  return *(unsigned*)&h;
}
__device__ __forceinline__ void mma16816(float* c, const unsigned* a, unsigned b0, unsigned b1){
  asm volatile("mma.sync.aligned.m16n8k16.row.col.f32.bf16.bf16.f32 "
      "{%0,%1,%2,%3}, {%4,%5,%6,%7}, {%8,%9}, {%0,%1,%2,%3};\n"
      : "+f"(c[0]), "+f"(c[1]), "+f"(c[2]), "+f"(c[3])
      : "r"(a[0]), "r"(a[1]), "r"(a[2]), "r"(a[3]), "r"(b0), "r"(b1));
}

__global__ void __launch_bounds__(256, 2) gemm_mma(const float* __restrict__ A,
                                                   const float* __restrict__ Bm,
                                                   float* __restrict__ C,
                                                   int M, int N, int K) {
  __shared__ unsigned Ah[128*APAD];
  __shared__ unsigned Al[128*APAD];
  __shared__ unsigned Bh[16*BPAD];
  __shared__ unsigned Bl[16*BPAD];
  int t = threadIdx.x;
  int lane = t & 31, wid = t >> 5;
  int g = lane >> 2, tg = lane & 3;
  int wm = (wid >> 2) * 64;          // 0 or 64
  int wn = (wid & 3) * 32;           // 0..96
  int bx = blockIdx.x, by = blockIdx.y;

  float acc[4][4][4];
  #pragma unroll
  for (int i=0;i<4;i++)
    #pragma unroll
    for (int j=0;j<4;j++)
      #pragma unroll
      for (int r=0;r<4;r++) acc[i][j][r] = 0.f;

  // A loader: row = t>>1 (0..127), 16 consecutive k-cols at (t&1)*16
  int arow = t >> 1, ahalf = (t & 1) * 16;
  const float* Aptr = A + (size_t)(by*128 + arow)*K + ahalf;
  // B loader: k-pair = t>>4 (0..15), 8 consecutive n-cols at (t&15)*8
  int bkp = t >> 4, bcb = (t & 15) * 8;
  const float* Bptr0 = Bm + (size_t)(2*bkp)*N + bx*128 + bcb;
  const float* Bptr1 = Bptr0 + N;

  for (int k0 = 0; k0 < K; k0 += 32) {
    __syncthreads();
    // stage + split A tile: 128x32 fp32 -> Ah/Al (k-pair packed along k)
    #pragma unroll
    for (int q = 0; q < 4; q++) {
      float4 v = *(const float4*)(Aptr + k0 + q*4);
      int pi = (ahalf >> 1) + q*2;
      uint2 hv = make_uint2(pk_hi(v.x, v.y), pk_hi(v.z, v.w));
      uint2 lv = make_uint2(pk_lo(v.x, v.y), pk_lo(v.z, v.w));
      *(uint2*)&Ah[arow*APAD + pi] = hv;
      *(uint2*)&Al[arow*APAD + pi] = lv;
    }
    // stage + split B tile: 32x128 fp32 -> Bh/Bl ([kpair][n], pair packed along k)
    #pragma unroll
    for (int q = 0; q < 2; q++) {
      float4 r0 = *(const float4*)(Bptr0 + (size_t)k0*N + q*4);
      float4 r1 = *(const float4*)(Bptr1 + (size_t)k0*N + q*4);
      int nb = bcb + q*4;
      uint4 hv = make_uint4(pk_hi(r0.x, r1.x), pk_hi(r0.y, r1.y),
                            pk_hi(r0.z, r1.z), pk_hi(r0.w, r1.w));
      uint4 lv = make_uint4(pk_lo(r0.x, r1.x), pk_lo(r0.y, r1.y),
                            pk_lo(r0.z, r1.z), pk_lo(r0.w, r1.w));
      *(uint4*)&Bh[bkp*BPAD + nb] = hv;
      *(uint4*)&Bl[bkp*BPAD + nb] = lv;
    }
    __syncthreads();
    // compute: 2 x k16 steps
    #pragma unroll
    for (int ks = 0; ks < 2; ks++) {
      unsigned afh[4][4], afl[4][4];
      #pragma unroll
      for (int i = 0; i < 4; i++) {
        int r0 = wm + i*16 + g;
        int c0 = ks*8 + tg;
        afh[i][0] = Ah[r0*APAD + c0];
        afh[i][1] = Ah[(r0+8)*APAD + c0];
        afh[i][2] = Ah[r0*APAD + c0 + 4];
        afh[i][3] = Ah[(r0+8)*APAD + c0 + 4];
        afl[i][0] = Al[r0*APAD + c0];
        afl[i][1] = Al[(r0+8)*APAD + c0];
        afl[i][2] = Al[r0*APAD + c0 + 4];
        afl[i][3] = Al[(r0+8)*APAD + c0 + 4];
      }
      #pragma unroll
      for (int j = 0; j < 4; j++) {
        int nn = wn + j*8 + g;
        int kp = ks*8 + tg;
        unsigned bh0 = Bh[kp*BPAD + nn], bh1 = Bh[(kp+4)*BPAD + nn];
        unsigned bl0 = Bl[kp*BPAD + nn], bl1 = Bl[(kp+4)*BPAD + nn];
        #pragma unroll
        for (int i = 0; i < 4; i++) {
          mma16816(acc[i][j], afh[i], bh0, bh1);
          mma16816(acc[i][j], afh[i], bl0, bl1);
          mma16816(acc[i][j], afl[i], bh0, bh1);
        }
      }
    }
  }
  // epilogue
  #pragma unroll
  for (int i = 0; i < 4; i++) {
    int row = by*128 + wm + i*16 + g;
    #pragma unroll
    for (int j = 0; j < 4; j++) {
      int col = bx*128 + wn + j*8 + tg*2;
      *(float2*)&C[(size_t)row*N + col]     = make_float2(acc[i][j][0], acc[i][j][1]);
      *(float2*)&C[(size_t)(row+8)*N + col] = make_float2(acc[i][j][2], acc[i][j][3]);
    }
  }
}

// ---------------- pointwise: dt, adt, g1, g2 ----------------
__global__ void k_point(const float* __restrict__ dt_bias) {
  int idx = blockIdx.x*256 + threadIdx.x;
  if (idx >= BB*LL*NH) return;
  int h = idx % NH; int bl = idx / NH; int l = bl % LL;
  size_t base = (size_t)bl * DPROJ;
  float db = dt_bias[h];
  float dt = sp_(g_proj[base + 4352 + h] + db);
  float a  = fminf(-sp_(g_proj[base + 4384 + h]), -1e-4f);
  float adt = a * dt;
  float beta = sigm_(g_proj[base + 4416 + h]);
  float dtp = (l > 0) ? sp_(g_proj[base - DPROJ + 4352 + h] + db) : 0.f;
  g_dt[idx]  = dt;
  g_adt[idx] = adt;
  g_g1[idx]  = beta * dt;
  g_g2[idx]  = (1.f - beta) * expf(adt) * dtp;
}

// ---------------- theta cumsum over L (parallel scan) ----------------
__global__ void __launch_bounds__(1024) k_theta2() {
  int b = blockIdx.x / NH, h = blockIdx.x % NH;
  int t = threadIdx.x;
  int a = t & 31;
  int s = t >> 5;
  __shared__ float ss[32][33];
  const float* pang = g_proj + (size_t)b*LL*DPROJ + 4448 + a;
  const float* pdt  = g_dt  + (size_t)b*LL*NH + h;
  int l0 = s*64;
  float loc = 0.f;
  for (int l=l0; l<l0+64; l++)
    loc += pang[(size_t)l*DPROJ] * pdt[(size_t)l*NH];
  ss[s][a] = loc;
  __syncthreads();
  float run = 0.f;
  for (int sp=0; sp<s; sp++) run += ss[sp][a];
  for (int l=l0; l<l0+64; l++){
    run += pang[(size_t)l*DPROJ] * pdt[(size_t)l*NH];
    g_theta[((size_t)(b*LL + l)*NH + h)*NA + a] = run;
  }
}

// ---------------- RMSNorm + bias + RoPE -> Q, K ----------------
__global__ void __launch_bounds__(128) k_qk(const float* __restrict__ B_bias,
                                            const float* __restrict__ C_bias,
                                            const float* __restrict__ Bw,
                                            const float* __restrict__ Cw) {
  int bl = blockIdx.x;
  int p = threadIdx.x;
  __shared__ float Bn[DS], Cn[DS];
  __shared__ float rs[4][2];
  size_t base = (size_t)bl * DPROJ;
  float bg = g_proj[base + 4096 + p];
  float cg = g_proj[base + 4224 + p];
  float sb = bg*bg, sc = cg*cg;
  #pragma unroll
  for (int o=16;o>0;o>>=1){
    sb += __shfl_xor_sync(0xffffffff, sb, o);
    sc += __shfl_xor_sync(0xffffffff, sc, o);
  }
  if ((p&31)==0){ rs[p>>5][0]=sb; rs[p>>5][1]=sc; }
  __syncthreads();
  float tb = rs[0][0]+rs[1][0]+rs[2][0]+rs[3][0];
  float tc = rs[0][1]+rs[1][1]+rs[2][1]+rs[3][1];
  float rB = rsqrtf(tb/(float)DS + EPSF);
  float rC = rsqrtf(tc/(float)DS + EPSF);
  Bn[p] = bg*rB*Bw[p];
  Cn[p] = cg*rC*Cw[p];
  __syncthreads();
  const float* th = g_theta + (size_t)bl*NH*NA;
  for (int h=0; h<NH; h++){
    float outK, outQ;
    if (p < 64) {
      int a = p & 31;
      float ang = th[h*NA + a];
      float c = cosf(ang), s = sinf(ang);
      if (p < 32) {
        float k1 = Bn[p]    + B_bias[h*DS+p];
        float k2 = Bn[p+32] + B_bias[h*DS+p+32];
        outK = k1*c - k2*s;
        float q1 = Cn[p]    + C_bias[h*DS+p];
        float q2 = Cn[p+32] + C_bias[h*DS+p+32];
        outQ = q1*c - q2*s;
      } else {
        float k1 = Bn[a] + B_bias[h*DS+a];
        float k2 = Bn[p] + B_bias[h*DS+p];
        outK = k1*s + k2*c;
        float q1 = Cn[a] + C_bias[h*DS+a];
        float q2 = Cn[p] + C_bias[h*DS+p];
        outQ = q1*s + q2*c;
      }
    } else {
      outK = Bn[p] + B_bias[h*DS+p];
      outQ = Cn[p] + C_bias[h*DS+p];
    }
    size_t o = ((size_t)bl*NH + h)*DS + p;
    g_K[o] = outK;
    g_Q[o] = outQ;
  }
}

// ---------------- chunk kernel: S1/S2, y_intra, Wsum (512 threads) ----------------
// S1/S2 alias the Qs region after phase A => 83 KB smem => 2 blocks/SM.
#define QSS 129
#define SMEM_CHUNK ((64*QSS + 65*QSS + 65*64)*4)
__global__ void __launch_bounds__(512, 2) k_chunk() {
  extern __shared__ float sm[];
  float* Qs = sm;                  // 64 x 129  (phase A only)
  float* Ke = Qs + 64*QSS;         // 65 x 129 (row r = token l0+r-1)
  float* xe = Ke + 65*QSS;         // 65 x 64
  float* S1 = sm;                  // 64 x 64, aliases Qs after phase A
  float* S2 = sm + 4096;           // 64 x 64  (8192 <= 64*129 floats, fits)
  __shared__ float ell[CK], g1s[CK], g2s[CK], w1s[CK], w2s[CK];
  int t = threadIdx.x;
  int bid = blockIdx.x;
  int h = bid % NH; int c = (bid/NH) % NC; int b = bid/(NH*NC);
  int l0 = c*CK;
  size_t qbase = ((size_t)(b*LL + l0)*NH + h)*DS;
  for (int idx=t; idx<64*DS; idx+=512){
    int i = idx >> 7, n = idx & 127;
    Qs[i*QSS+n] = g_Q[qbase + (size_t)i*NH*DS + n];
  }
  for (int idx=t; idx<65*DS; idx+=512){
    int r = idx >> 7, n = idx & 127;
    int l = l0 + r - 1;
    Ke[r*QSS+n] = (l >= 0) ? g_K[((size_t)(b*LL + l)*NH + h)*DS + n] : 0.f;
  }
  for (int idx=t; idx<65*HD; idx+=512){
    int r = idx >> 6, pp = idx & 63;
    int l = l0 + r - 1;
    xe[r*64+pp] = (l >= 0) ? g_proj[(size_t)(b*LL + l)*DPROJ + DIN + h*HD + pp] : 0.f;
  }
  if (t < CK) {
    int gi = (b*LL + l0 + t)*NH + h;
    g1s[t] = g_g1[gi]; g2s[t] = g_g2[gi];
    ell[t] = g_adt[gi];
  }
  __syncthreads();
  if (t == 0) {
    float run = 0.f;
    for (int j=0;j<CK;j++){ run += ell[j]; ell[j] = run; }
  }
  __syncthreads();
  if (t < CK) {
    float e63 = ell[CK-1];
    float de = expf(e63 - ell[t]);
    w1s[t] = g1s[t]*de; w2s[t] = g2s[t]*de;
    g_eell[(b*LL + l0 + t)*NH + h] = expf(ell[t]);
    if (t == 0) g_cd[bid] = expf(e63);
  }
  __syncthreads();
  // Phase A: compute S values into registers (reads Qs), then write into
  // the Qs region after a sync (Qs dead from then on).
  {
    int i = t >> 3;
    int js = (t & 7) * 8;
    float a1[8], a2[8];
    #pragma unroll
    for (int jj=0;jj<8;jj++){ a1[jj]=0.f; a2[jj]=0.f; }
    for (int n=0;n<DS;n++){
      float q = Qs[i*QSS+n];
      float kv[9];
      #pragma unroll
      for (int r=0;r<9;r++) kv[r] = Ke[(js+r)*QSS+n];
      #pragma unroll
      for (int jj=0;jj<8;jj++){
        a1[jj] += q*kv[jj+1];
        a2[jj] += q*kv[jj];
      }
    }
    float ei = ell[i];
    #pragma unroll
    for (int jj=0;jj<8;jj++){
      int j = js + jj;
      float d = (j <= i) ? expf(ei - ell[j]) : 0.f;
      a1[jj] = a1[jj]*g1s[j]*d;
      a2[jj] = a2[jj]*g2s[j]*d;
    }
    __syncthreads();   // all Qs reads complete before aliasing writes
    #pragma unroll
    for (int jj=0;jj<8;jj++){
      S1[i*64+js+jj] = a1[jj];
      S2[i*64+js+jj] = a2[jj];
    }
  }
  __syncthreads();
  // Phase B: y_intra -> g_y  (thread: i = t>>3, p = (t&7) + 8*pp)
  {
    int i = t >> 3;
    int pb = t & 7;
    float acc[8];
    #pragma unroll
    for (int pp=0;pp<8;pp++) acc[pp]=0.f;
    for (int j=0;j<=i;j++){
      float s1 = S1[i*64+j], s2 = S2[i*64+j];
      #pragma unroll
      for (int pp=0;pp<8;pp++){
        int p = pb + pp*8;
        acc[pp] += s1*xe[(j+1)*64+p] + s2*xe[j*64+p];
      }
    }
    size_t yb = (size_t)(b*LL + l0 + i)*DIN + h*HD + pb;
    #pragma unroll
    for (int pp=0;pp<8;pp++) g_y[yb + pp*8] = acc[pp];
  }
  // Phase C: Wsum[p][n] -> g_W  (thread: p = t>>3, n = (t&7) + 8*nn)
  {
    int p = t >> 3;
    int nb = t & 7;
    float acc[16];
    #pragma unroll
    for (int nn=0;nn<16;nn++) acc[nn]=0.f;
    for (int j=0;j<CK;j++){
      float a1 = w1s[j]*xe[(j+1)*64+p];
      float a2 = w2s[j]*xe[j*64+p];
      #pragma unroll
      for (int nn=0;nn<16;nn++){
        int n = nb + nn*8;
        acc[nn] += a1*Ke[(j+1)*QSS+n] + a2*Ke[j*QSS+n];
      }
    }
    size_t wb = ((size_t)bid*HD + p)*DS + nb;
    #pragma unroll
    for (int nn=0;nn<16;nn++) g_W[wb + nn*8] = acc[nn];
  }
}

// ---------------- inter-chunk state scan (in place: Wsum -> Hprev), 256 blocks ----------------
__global__ void __launch_bounds__(256) k_scan2() {
  int blk = blockIdx.x;
  int bh = blk >> 2, part = blk & 3;
  int b = bh / NH, h = bh % NH;
  int e0 = part*2048 + threadIdx.x*8;
  float H[8];
  #pragma unroll
  for (int r=0;r<8;r++) H[r]=0.f;
  for (int c=0;c<NC;c++){
    int bid = (b*NC + c)*NH + h;
    float cd = g_cd[bid];
    float* p = g_W + (size_t)bid*(HD*DS) + e0;
    float4 w0 = *(float4*)p;
    float4 w1 = *(float4*)(p+4);
    *(float4*)p     = make_float4(H[0],H[1],H[2],H[3]);
    *(float4*)(p+4) = make_float4(H[4],H[5],H[6],H[7]);
    H[0]=cd*H[0]+w0.x; H[1]=cd*H[1]+w0.y; H[2]=cd*H[2]+w0.z; H[3]=cd*H[3]+w0.w;
    H[4]=cd*H[4]+w1.x; H[5]=cd*H[5]+w1.y; H[6]=cd*H[6]+w1.z; H[7]=cd*H[7]+w1.w;
  }
}

// ---------------- y_inter + D*x + SiLU gating ----------------
#define SMEM_INTER ((64*QSS*2)*4)
__global__ void __launch_bounds__(256) k_inter(const float* __restrict__ Dp) {
  extern __shared__ float sm[];
  float* Hs = sm;
  float* Qs = Hs + 64*QSS;
  __shared__ float eel[CK];
  int t = threadIdx.x;
  int bid = blockIdx.x;
  int h = bid % NH; int c = (bid/NH)%NC; int b = bid/(NH*NC);
  int l0 = c*CK;
  size_t wbase = (size_t)bid*HD*DS;
  for (int idx=t; idx<HD*DS; idx+=256){
    int p = idx>>7, n = idx&127;
    Hs[p*QSS+n] = g_W[wbase + idx];
  }
  size_t qbase = ((size_t)(b*LL+l0)*NH + h)*DS;
  for (int idx=t; idx<CK*DS; idx+=256){
    int i = idx>>7, n = idx&127;
    Qs[i*QSS+n] = g_Q[qbase + (size_t)i*NH*DS + n];
  }
  if (t < CK) eel[t] = g_eell[(b*LL+l0+t)*NH + h];
  __syncthreads();
  int i = t>>2, ps = (t&3)*16;
  float acc[16];
  #pragma unroll
  for (int pp=0;pp<16;pp++) acc[pp]=0.f;
  for (int n=0;n<DS;n++){
    float q = Qs[i*QSS+n];
    #pragma unroll
    for (int pp=0;pp<16;pp++) acc[pp] += q*Hs[(ps+pp)*QSS+n];
  }
  float e = eel[i];
  float dv = Dp[h];
  size_t pb = (size_t)(b*LL+l0+i)*DPROJ;
  size_t yb = (size_t)(b*LL+l0+i)*DIN + h*HD + ps;
  #pragma unroll
  for (int pp=0;pp<16;pp++){
    float x = g_proj[pb + DIN + h*HD + ps + pp];
    float z = g_proj[pb + h*HD + ps + pp];
    float y = g_y[yb+pp] + e*acc[pp] + dv*x;
    g_y[yb+pp] = y * (z * sigm_(z));
  }
}

extern "C" void kernel_launch(void* const* d_in, const int* in_sizes, int n_in,
                              void* d_out, int out_size) {
  const float* u        = (const float*)d_in[0];
  const float* W_in     = (const float*)d_in[1];
  const float* W_out    = (const float*)d_in[2];
  const float* dt_bias  = (const float*)d_in[3];
  const float* B_bias   = (const float*)d_in[4];
  const float* C_bias   = (const float*)d_in[5];
  const float* B_norm_w = (const float*)d_in[6];
  const float* C_norm_w = (const float*)d_in[7];
  const float* Dv       = (const float*)d_in[8];
  float* out = (float*)d_out;
  (void)in_sizes; (void)n_in; (void)out_size;

  float *proj, *y;
  cudaGetSymbolAddress((void**)&proj, g_proj);
  cudaGetSymbolAddress((void**)&y, g_y);

  cudaFuncSetAttribute(k_chunk, cudaFuncAttributeMaxDynamicSharedMemorySize, SMEM_CHUNK);
  cudaFuncSetAttribute(k_inter, cudaFuncAttributeMaxDynamicSharedMemorySize, SMEM_INTER);

  // 1. proj = u @ W_in : [4096,1024]x[1024,4480]  (bf16-split mma.sync GEMM)
  gemm_mma<<<dim3(DPROJ/128, (BB*LL)/128), 256>>>(u, W_in, proj, BB*LL, DPROJ, DM);
  // 2. dt / adt / g1 / g2
  k_point<<<(BB*LL*NH + 255)/256, 256>>>(dt_bias);
  // 3. theta cumsum (parallel scan)
  k_theta2<<<BB*NH, 1024>>>();
  // 4. rmsnorm + rope -> Q, K
  k_qk<<<BB*LL, DS>>>(B_bias, C_bias, B_norm_w, C_norm_w);
  // 5. intra-chunk: S, y_intra, Wsum
  k_chunk<<<BB*NC*NH, 512, SMEM_CHUNK>>>();
  // 6. inter-chunk scan
  k_scan2<<<BB*NH*4, 256>>>();
  // 7. y_inter + gating
  k_inter<<<BB*NC*NH, 256, SMEM_INTER>>>(Dv);
  // 8. out = y @ W_out : [4096,2048]x[2048,1024]  (bf16-split mma.sync GEMM)
  gemm_mma<<<dim3(DM/128, (BB*LL)/128), 256>>>(y, W_out, out, BB*LL, DM, DIN);
}